// round 4
// baseline (speedup 1.0000x reference)
#include <cuda_runtime.h>
#include <cuda_bf16.h>

// NeighborIntegration: B=64, K=64, D=128
//
// y[b,i] = 0.5*( (64*mask_c*concept[b,i] + sum_j mask_n*neigh[b,i,j]) @ W1a
//              + (64*mask_c + cnt_n) * (stu[b] @ W1b + b1) )
//
// Kernel 0 (tiny): a2[b,:] = stu[b] @ W1b + b1   (64 x 128, hoisted globally)
// Kernel 1: one block per (b,i), 8 warps.
//   Phase 1: 8 warps x 8 rows masked streaming reduction (MLP=8/warp).
//   Phase 2: combine + masks in smem.
//   Phase 3: v @ W1a split-k across 8 warps (k-slice of 16 each), float4 rows.

#define D_ 128
#define K_ 64

__device__ float g_a2[64 * D_];   // stu @ W1b + b1, per batch row

__device__ __forceinline__ float warp_sum(float x) {
#pragma unroll
    for (int o = 16; o > 0; o >>= 1)
        x += __shfl_xor_sync(0xffffffffu, x, o);
    return x;
}

__global__ __launch_bounds__(128)
void a2_kernel(const float* __restrict__ stu, const float* __restrict__ W1,
               const float* __restrict__ b1)
{
    const int b = blockIdx.x;
    const int d = threadIdx.x;
    __shared__ float s_stu[D_];
    s_stu[d] = stu[b * D_ + d];
    __syncthreads();
    float p = b1[d];
#pragma unroll 8
    for (int k = 0; k < D_; ++k)
        p = fmaf(s_stu[k], W1[(size_t)(D_ + k) * D_ + d], p);
    g_a2[b * D_ + d] = p;
}

__global__ __launch_bounds__(256)
void neighbor_integration_kernel(const float* __restrict__ concept_,  // [64,64,128]
                                 const float* __restrict__ neigh,     // [64,64,64,128]
                                 const float* __restrict__ W1,        // [256,128]
                                 float* __restrict__ out)             // [64,64,128]
{
    const int bi   = blockIdx.x;        // b*64 + i
    const int b    = bi >> 6;
    const int tid  = threadIdx.x;
    const int w    = tid >> 5;          // warp 0..7
    const int lane = tid & 31;

    __shared__ float  s_acc[8][D_];     // per-warp masked row accumulators
    __shared__ float  s_cnt[8];         // per-warp masked-row counts
    __shared__ float  s_red[4];         // concept-sum partials
    __shared__ float  s_v[D_];          // GEMV input vector
    __shared__ float4 s_part[8][32];    // GEMV partials per warp

    // ---------------- Phase 1: masked reduction over j -------------------
    const float4* nbase = reinterpret_cast<const float4*>(neigh) +
                          (size_t)bi * (K_ * 32);
    float4 r[8];
#pragma unroll
    for (int u = 0; u < 8; ++u)
        r[u] = __ldcs(&nbase[(w * 8 + u) * 32 + lane]);   // MLP=8/warp

    float4 acc = make_float4(0.f, 0.f, 0.f, 0.f);
    float  cnt = 0.f;
#pragma unroll
    for (int u = 0; u < 8; ++u) {
        const float rs = warp_sum((r[u].x + r[u].y) + (r[u].z + r[u].w));
        if (rs != 0.0f) {               // mask_n (warp-uniform predicate)
            acc.x += r[u].x; acc.y += r[u].y;
            acc.z += r[u].z; acc.w += r[u].w;
            cnt   += 1.0f;
        }
    }
    reinterpret_cast<float4*>(s_acc[w])[lane] = acc;
    if (lane == 0) s_cnt[w] = cnt;
    __syncthreads();

    // ---------------- Phase 2: combine + concept mask ---------------------
    float R = 0.f, c = 0.f;
    if (tid < D_) {
#pragma unroll
        for (int ww = 0; ww < 8; ++ww) R += s_acc[ww][tid];
        c = concept_[(size_t)bi * D_ + tid];
    }
    const float cs = warp_sum(c);       // warps 0..3 hold concept data
    if (lane == 0 && w < 4) s_red[w] = cs;
    __syncthreads();

    const float csum = s_red[0] + s_red[1] + s_red[2] + s_red[3];
    const float mc   = (csum != 0.0f) ? 64.0f : 0.0f;   // 64*mask_c
    if (tid < D_)
        s_v[tid] = fmaf(mc, c, R);
    __syncthreads();

    // ---------------- Phase 3: v @ W1a, split-k over 8 warps --------------
    // Warp w: k in [16w, 16w+16). Lane owns d = 4*lane..4*lane+3 partials.
    float4 o = make_float4(0.f, 0.f, 0.f, 0.f);
    const int kbase = w * 16;
#pragma unroll
    for (int kk = 0; kk < 16; ++kk) {
        const int k = kbase + kk;
        const float vk = s_v[k];                         // LDS broadcast
        const float4 wr = reinterpret_cast<const float4*>(
                              W1 + (size_t)k * D_)[lane]; // LDG.128, L1-hot
        o.x = fmaf(vk, wr.x, o.x);
        o.y = fmaf(vk, wr.y, o.y);
        o.z = fmaf(vk, wr.z, o.z);
        o.w = fmaf(vk, wr.w, o.w);
    }
    s_part[w][lane] = o;
    __syncthreads();

    // ---------------- Phase 4: reduce partials, epilogue ------------------
    if (tid < D_) {
        const float* sp = reinterpret_cast<const float*>(s_part);
        float od = 0.f;
#pragma unroll
        for (int ww = 0; ww < 8; ++ww) od += sp[ww * D_ + tid];

        const float cntn = s_cnt[0] + s_cnt[1] + s_cnt[2] + s_cnt[3] +
                           s_cnt[4] + s_cnt[5] + s_cnt[6] + s_cnt[7];
        const float scale = mc + cntn;
        const float a2 = g_a2[b * D_ + tid];
        out[(size_t)bi * D_ + tid] = 0.5f * fmaf(scale, a2, od);
    }
}

extern "C" void kernel_launch(void* const* d_in, const int* in_sizes, int n_in,
                              void* d_out, int out_size)
{
    const float* stu      = (const float*)d_in[0];  // [64,128]
    const float* concept_ = (const float*)d_in[1];  // [64,64,128]
    const float* neigh    = (const float*)d_in[2];  // [64,64,64,128]
    const float* W1       = (const float*)d_in[3];  // [256,128]
    const float* b1       = (const float*)d_in[4];  // [128]
    // d_in[5]=Wn, d_in[6]=bn: dead (softmax over size-1 axis == 1)
    float* out = (float*)d_out;

    a2_kernel<<<64, 128>>>(stu, W1, b1);
    neighbor_integration_kernel<<<64 * 64, 256>>>(concept_, neigh, W1, out);
}